// round 8
// baseline (speedup 1.0000x reference)
#include <cuda_runtime.h>
#include <cuda_bf16.h>
#include <cstdint>

// ============================ problem constants ============================
#define NROWS 65536
#define DDIM  512
#define KCL   1024

// ============================ device scratch ===============================
__device__ __nv_bfloat16 g_cbf[KCL * DDIM];   // clusters in bf16 (1 MB)
__device__ float g_csq[KCL];                  // ||c||^2 (exact fp32)

// ============================ helpers ======================================
__device__ __forceinline__ uint32_t smem_to_u32(const void* p) {
    uint32_t a;
    asm("{ .reg .u64 t; cvta.to.shared.u64 t, %1; cvt.u32.u64 %0, t; }"
        : "=r"(a) : "l"(p));
    return a;
}

__device__ __forceinline__ uint32_t pack_bf2(float a, float b) {
    __nv_bfloat162 h = __floats2bfloat162_rn(a, b);
    return *reinterpret_cast<uint32_t*>(&h);
}

// swizzled smem byte offset for (row, 16B-chunk) within a [rows x 64B] tile.
__device__ __forceinline__ uint32_t swz(uint32_t row, uint32_t chunk) {
    return (row << 6) + (((chunk) ^ ((row >> 1) & 3u)) << 4);
}

#define CP_ASYNC_16(saddr, gaddr) \
    asm volatile("cp.async.cg.shared.global [%0], [%1], 16;" \
                 :: "r"(saddr), "l"(gaddr))
#define CP_COMMIT() asm volatile("cp.async.commit_group;" ::: "memory")
#define CP_WAIT_1() asm volatile("cp.async.wait_group 1;" ::: "memory")
#define CP_WAIT_0() asm volatile("cp.async.wait_group 0;" ::: "memory")

#define LDSM_X4(r0, r1, r2, r3, addr) \
    asm volatile("ldmatrix.sync.aligned.m8n8.x4.shared.b16 {%0,%1,%2,%3}, [%4];" \
                 : "=r"(r0), "=r"(r1), "=r"(r2), "=r"(r3) : "r"(addr))

#define MMA_BF16(d0, d1, d2, d3, a0, a1, a2, a3, b0, b1) \
    asm volatile("mma.sync.aligned.m16n8k16.row.col.f32.bf16.bf16.f32 " \
                 "{%0,%1,%2,%3}, {%4,%5,%6,%7}, {%8,%9}, {%0,%1,%2,%3};" \
                 : "+f"(d0), "+f"(d1), "+f"(d2), "+f"(d3) \
                 : "r"(a0), "r"(a1), "r"(a2), "r"(a3), "r"(b0), "r"(b1))

// ============================ prep kernel ==================================
__global__ void prep_clusters(const float* __restrict__ cl) {
    int k = blockIdx.x;
    int t = threadIdx.x;  // 128 threads, one float4 each
    float4 v = reinterpret_cast<const float4*>(cl + (size_t)k * DDIM)[t];
    uint2 p = { pack_bf2(v.x, v.y), pack_bf2(v.z, v.w) };
    reinterpret_cast<uint2*>(g_cbf + (size_t)k * DDIM)[t] = p;
    float s = v.x * v.x + v.y * v.y + v.z * v.z + v.w * v.w;
    for (int o = 16; o; o >>= 1) s += __shfl_down_sync(0xFFFFFFFFu, s, o);
    __shared__ float ps[4];
    if ((t & 31) == 0) ps[t >> 5] = s;
    __syncthreads();
    if (t == 0) g_csq[k] = ps[0] + ps[1] + ps[2] + ps[3];
}

// ============================ main kernel ==================================
// One CTA per 128-row block, 512 threads (16 warps, 4M x 4N, warp tile 32x32).
// A (128x512 bf16, 128KB) smem-resident; 8 N-tiles of 128 cols; K-step 64
// per barrier window. B via 3-stage x 16KB cp.async ring. Row sums in regs.
static constexpr int A_BYTES    = 128 * 512 * 2;               // 131072
static constexpr int A_CHUNK    = 128 * 64;                    // 8192 (128 rows x 64B)
static constexpr int B_OFF      = A_BYTES;
static constexpr int B_STAGE    = 16384;                       // 128 N-rows x 128B
static constexpr int NSTAGE     = 3;
static constexpr int XSQ_OFF    = B_OFF + NSTAGE * B_STAGE;    // 180224 (128 f)
static constexpr int SMEM_TOTAL = XSQ_OFF + 512;               // 180736
// post-loop aliases into the dead B ring:
static constexpr int PS_OFF     = B_OFF;                       // [128][4] f
static constexpr int RSUM_OFF   = B_OFF + 2048;                // [128] f

__global__ void __launch_bounds__(512, 1)
cluster_main_kernel(const float* __restrict__ x, float* __restrict__ out) {
    extern __shared__ char smem[];
    const uint32_t sb = smem_to_u32(smem);
    const int t  = threadIdx.x;
    const int rowbase = blockIdx.x * 128;

    const int w  = t >> 5;                    // warp id 0..15
    const int l  = t & 31;                    // lane
    const int wm = w >> 2;                    // 0..3 (M, 32 rows)
    const int wn = w & 3;                     // 0..3 (N, 32 cols)
    const int group = l >> 2;                 // 0..7
    const int tid4  = l & 3;                  // 0..3

    float* xsq_s = reinterpret_cast<float*>(smem + XSQ_OFF);

    // ---- B loader (hoisted addressing). idx in [0,64): nt=idx>>3, kcp=idx&7 ----
    // stage = 2 sub-chunks of 128 rows x 64B; 512 threads -> 1 chunk/thread/sub.
    const int brow = t >> 2, bch = t & 3;
    const uint32_t bswz = swz((uint32_t)brow, (uint32_t)bch);
    auto load_B = [&](int idx, int slot) {
        const int nt = idx >> 3, kcp = idx & 7;
        const uint32_t s = sb + B_OFF + slot * B_STAGE;
        const __nv_bfloat16* cbT =
            g_cbf + (size_t)(nt * 128 + brow) * DDIM + kcp * 64 + bch * 8;
        CP_ASYNC_16(s + bswz,        (uint64_t)__cvta_generic_to_global(cbT));
        CP_ASYNC_16(s + 8192 + bswz, (uint64_t)__cvta_generic_to_global(cbT + 32));
    };

    // prologue: prefetch 2 stages, then convert A while they fly
    load_B(0, 0); CP_COMMIT();
    load_B(1, 1); CP_COMMIT();

    // ---- prologue: fp32 x -> bf16 smem A + x_sq (4 threads per row) ----
    {
        const int r  = t >> 2;             // local row 0..127
        const int cb = (t & 3) * 128;      // col base, 128 cols per thread
        const float* xr = x + (size_t)(rowbase + r) * DDIM + cb;
        float s = 0.f;
        #pragma unroll
        for (int i = 0; i < 16; ++i) {
            const int col = cb + i * 8;
            float4 f0 = reinterpret_cast<const float4*>(xr + i * 8)[0];
            float4 f1 = reinterpret_cast<const float4*>(xr + i * 8)[1];
            s += f0.x * f0.x + f0.y * f0.y + f0.z * f0.z + f0.w * f0.w
               + f1.x * f1.x + f1.y * f1.y + f1.z * f1.z + f1.w * f1.w;
            uint32_t p0 = pack_bf2(f0.x, f0.y), p1 = pack_bf2(f0.z, f0.w);
            uint32_t p2 = pack_bf2(f1.x, f1.y), p3 = pack_bf2(f1.z, f1.w);
            const int kc = col >> 5, j = (col & 31) >> 3;
            uint32_t dst = sb + kc * A_CHUNK + swz((uint32_t)r, (uint32_t)j);
            asm volatile("st.shared.v4.b32 [%0], {%1, %2, %3, %4};"
                         :: "r"(dst), "r"(p0), "r"(p1), "r"(p2), "r"(p3));
        }
        s += __shfl_xor_sync(0xFFFFFFFFu, s, 1);
        s += __shfl_xor_sync(0xFFFFFFFFu, s, 2);
        if (tid4 == 0) xsq_s[r] = s;
    }
    __syncthreads();

    // this thread's row squared-norms, in registers for all epilogues
    const int er0 = wm * 32 + group;
    float xs[2][2];
    #pragma unroll
    for (int mi = 0; mi < 2; ++mi) {
        xs[mi][0] = xsq_s[er0 + mi * 16];
        xs[mi][1] = xsq_s[er0 + mi * 16 + 8];
    }

    // ---- ldmatrix lane offsets (relative to 8KB A chunk / 8KB B sub-stage) ----
    uint32_t aAddr[2][2];
    {
        int r8   = (l & 7) + (((l >> 3) & 1) << 3);
        int cbit = l >> 4;
        #pragma unroll
        for (int mi = 0; mi < 2; ++mi) {
            int row = wm * 32 + mi * 16 + r8;
            aAddr[mi][0] = swz(row, cbit);
            aAddr[mi][1] = swz(row, 2 + cbit);
        }
    }
    uint32_t bAddr[2][2];
    {
        int m = l >> 3;
        #pragma unroll
        for (int p = 0; p < 2; ++p) {
            int row = wn * 32 + (p * 2 + (m >> 1)) * 8 + (l & 7);
            #pragma unroll
            for (int ks = 0; ks < 2; ++ks)
                bAddr[p][ks] = swz(row, 2 * ks + (m & 1));
        }
    }

    float acc[2][4][4];
    #pragma unroll
    for (int mi = 0; mi < 2; ++mi)
        #pragma unroll
        for (int nj = 0; nj < 4; ++nj)
            #pragma unroll
            for (int c = 0; c < 4; ++c) acc[mi][nj][c] = 0.f;

    float rs[2][2] = {{0.f, 0.f}, {0.f, 0.f}};   // running row sums

    // ---- 64-iteration pipeline: 8 N-tiles x 8 K-steps of 64 ----
    int cslot = 0;
    #pragma unroll 1
    for (int idx = 0; idx < 64; ++idx) {
        const int kcp = idx & 7;
        CP_WAIT_1();
        __syncthreads();
        {
            int lslot = cslot - 1; if (lslot < 0) lslot += 3;
            if (idx + 2 < 64) load_B(idx + 2, lslot);
            CP_COMMIT();
        }

        const uint32_t stg = sb + B_OFF + cslot * B_STAGE;
        if (++cslot == 3) cslot = 0;

        #pragma unroll
        for (int half = 0; half < 2; ++half) {
            const uint32_t sA = sb + (kcp * 2 + half) * A_CHUNK;
            const uint32_t sB = stg + half * 8192;
            #pragma unroll
            for (int ks = 0; ks < 2; ++ks) {
                uint32_t a[2][4], b[4][2];
                #pragma unroll
                for (int mi = 0; mi < 2; ++mi)
                    LDSM_X4(a[mi][0], a[mi][1], a[mi][2], a[mi][3], sA + aAddr[mi][ks]);
                #pragma unroll
                for (int p = 0; p < 2; ++p)
                    LDSM_X4(b[2*p][0], b[2*p][1], b[2*p+1][0], b[2*p+1][1],
                            sB + bAddr[p][ks]);
                #pragma unroll
                for (int mi = 0; mi < 2; ++mi)
                    #pragma unroll
                    for (int nj = 0; nj < 4; ++nj)
                        MMA_BF16(acc[mi][nj][0], acc[mi][nj][1],
                                 acc[mi][nj][2], acc[mi][nj][3],
                                 a[mi][0], a[mi][1], a[mi][2], a[mi][3],
                                 b[nj][0], b[nj][1]);
            }
        }

        // ---- N-tile epilogue (registers only; csq via __ldg, L2-resident) ----
        if (kcp == 7) {
            const int ntbase = (idx >> 3) * 128;
            #pragma unroll
            for (int mi = 0; mi < 2; ++mi) {
                #pragma unroll
                for (int nj = 0; nj < 4; ++nj) {
                    const int colL = wn * 32 + nj * 8 + tid4 * 2;
                    const float cs0 = __ldg(g_csq + ntbase + colL);
                    const float cs1 = __ldg(g_csq + ntbase + colL + 1);
                    float q00 = __fdividef(1.f, 1.f + fmaxf(xs[mi][0] + cs0 - 2.f * acc[mi][nj][0], 0.f));
                    float q01 = __fdividef(1.f, 1.f + fmaxf(xs[mi][0] + cs1 - 2.f * acc[mi][nj][1], 0.f));
                    float q10 = __fdividef(1.f, 1.f + fmaxf(xs[mi][1] + cs0 - 2.f * acc[mi][nj][2], 0.f));
                    float q11 = __fdividef(1.f, 1.f + fmaxf(xs[mi][1] + cs1 - 2.f * acc[mi][nj][3], 0.f));
                    rs[mi][0] += q00 + q01;
                    rs[mi][1] += q10 + q11;
                    acc[mi][nj][0] = 0.f; acc[mi][nj][1] = 0.f;
                    acc[mi][nj][2] = 0.f; acc[mi][nj][3] = 0.f;
                    const int r0 = wm * 32 + mi * 16 + group;
                    *reinterpret_cast<float2*>(
                        out + (size_t)(rowbase + r0) * KCL + ntbase + colL) = make_float2(q00, q01);
                    *reinterpret_cast<float2*>(
                        out + (size_t)(rowbase + r0 + 8) * KCL + ntbase + colL) = make_float2(q10, q11);
                }
            }
        }
    }

    // ---- final row-sum reduction (ps/rsum alias the dead B ring) ----
    CP_WAIT_0();
    __syncthreads();
    float* ps     = reinterpret_cast<float*>(smem + PS_OFF);   // [128][4]
    float* rsum_s = reinterpret_cast<float*>(smem + RSUM_OFF); // [128]
    #pragma unroll
    for (int mi = 0; mi < 2; ++mi) {
        float s0 = rs[mi][0], s1 = rs[mi][1];
        s0 += __shfl_xor_sync(0xFFFFFFFFu, s0, 1);
        s0 += __shfl_xor_sync(0xFFFFFFFFu, s0, 2);
        s1 += __shfl_xor_sync(0xFFFFFFFFu, s1, 1);
        s1 += __shfl_xor_sync(0xFFFFFFFFu, s1, 2);
        if (tid4 == 0) {
            const int r0 = wm * 32 + mi * 16 + group;
            ps[r0 * 4 + wn] = s0;
            ps[(r0 + 8) * 4 + wn] = s1;
        }
    }
    __syncthreads();
    if (t < 128)
        rsum_s[t] = __fdividef(1.f, ps[t * 4 + 0] + ps[t * 4 + 1] +
                                    ps[t * 4 + 2] + ps[t * 4 + 3]);
    __syncthreads();

    // ---- fused renormalization (512KB output slab, L2-resident) ----
    float4* op = reinterpret_cast<float4*>(out + (size_t)rowbase * KCL);
    #pragma unroll 4
    for (int i = 0; i < 64; ++i) {
        const int idx = i * 512 + t;
        const int r = idx >> 8;
        float iv = rsum_s[r];
        float4 v = op[idx];
        v.x *= iv; v.y *= iv; v.z *= iv; v.w *= iv;
        op[idx] = v;
    }
}

// ============================ launch =======================================
extern "C" void kernel_launch(void* const* d_in, const int* in_sizes, int n_in,
                              void* d_out, int out_size) {
    const float* x  = (const float*)d_in[0];   // (65536, 512)
    const float* cl = (const float*)d_in[1];   // (1024, 512)
    float* out = (float*)d_out;                // (65536, 1024)
    (void)in_sizes; (void)n_in; (void)out_size;

    cudaFuncSetAttribute(cluster_main_kernel,
                         cudaFuncAttributeMaxDynamicSharedMemorySize, SMEM_TOTAL);

    prep_clusters<<<KCL, 128>>>(cl);
    cluster_main_kernel<<<NROWS / 128, 512, SMEM_TOTAL>>>(x, out);
}

// round 9
// speedup vs baseline: 1.1140x; 1.1140x over previous
#include <cuda_runtime.h>
#include <cuda_bf16.h>
#include <cstdint>

// ============================ problem constants ============================
#define NROWS 65536
#define DDIM  512
#define KCL   1024

// ============================ device scratch ===============================
__device__ __nv_bfloat16 g_cbf[KCL * DDIM];   // clusters in bf16 (1 MB)
__device__ float g_csq[KCL];                  // ||c||^2 (exact fp32)

// ============================ helpers ======================================
__device__ __forceinline__ uint32_t smem_to_u32(const void* p) {
    uint32_t a;
    asm("{ .reg .u64 t; cvta.to.shared.u64 t, %1; cvt.u32.u64 %0, t; }"
        : "=r"(a) : "l"(p));
    return a;
}

__device__ __forceinline__ uint32_t pack_bf2(float a, float b) {
    __nv_bfloat162 h = __floats2bfloat162_rn(a, b);
    return *reinterpret_cast<uint32_t*>(&h);
}

// swizzled smem byte offset for (row, 16B-chunk) within a [rows x 64B] tile.
__device__ __forceinline__ uint32_t swz(uint32_t row, uint32_t chunk) {
    return (row << 6) + (((chunk) ^ ((row >> 1) & 3u)) << 4);
}

#define CP_ASYNC_16(saddr, gaddr) \
    asm volatile("cp.async.cg.shared.global [%0], [%1], 16;" \
                 :: "r"(saddr), "l"(gaddr))
#define CP_COMMIT() asm volatile("cp.async.commit_group;" ::: "memory")
#define CP_WAIT_2() asm volatile("cp.async.wait_group 2;" ::: "memory")
#define CP_WAIT_0() asm volatile("cp.async.wait_group 0;" ::: "memory")

#define LDSM_X4(r0, r1, r2, r3, addr) \
    asm volatile("ldmatrix.sync.aligned.m8n8.x4.shared.b16 {%0,%1,%2,%3}, [%4];" \
                 : "=r"(r0), "=r"(r1), "=r"(r2), "=r"(r3) : "r"(addr))

#define MMA_BF16(d0, d1, d2, d3, a0, a1, a2, a3, b0, b1) \
    asm volatile("mma.sync.aligned.m16n8k16.row.col.f32.bf16.bf16.f32 " \
                 "{%0,%1,%2,%3}, {%4,%5,%6,%7}, {%8,%9}, {%0,%1,%2,%3};" \
                 : "+f"(d0), "+f"(d1), "+f"(d2), "+f"(d3) \
                 : "r"(a0), "r"(a1), "r"(a2), "r"(a3), "r"(b0), "r"(b1))

// ============================ prep kernel ==================================
__global__ void prep_clusters(const float* __restrict__ cl) {
    int k = blockIdx.x;
    int t = threadIdx.x;  // 128 threads, one float4 each
    float4 v = reinterpret_cast<const float4*>(cl + (size_t)k * DDIM)[t];
    uint2 p = { pack_bf2(v.x, v.y), pack_bf2(v.z, v.w) };
    reinterpret_cast<uint2*>(g_cbf + (size_t)k * DDIM)[t] = p;
    float s = v.x * v.x + v.y * v.y + v.z * v.z + v.w * v.w;
    for (int o = 16; o; o >>= 1) s += __shfl_down_sync(0xFFFFFFFFu, s, o);
    __shared__ float ps[4];
    if ((t & 31) == 0) ps[t >> 5] = s;
    __syncthreads();
    if (t == 0) g_csq[k] = ps[0] + ps[1] + ps[2] + ps[3];
}

// ============================ main kernel ==================================
// One CTA per 64-row block, 2 CTAs/SM. A (64x512 bf16, 64KB) smem-resident.
// 8 N-tiles of 128 cols; K-step 64 per barrier window (2 sub-chunks of 32).
// B via 3-stage x 16KB cp.async ring, CP_WAIT_2 (only the needed stage must
// have landed; 2 groups stay in flight). Warps 2(M) x 4(N), warp tile 32x32.
// Row sums live in registers across tiles; ps/rsum alias the dead ring.
static constexpr int A_BYTES    = 64 * 512 * 2;                // 65536
static constexpr int B_OFF      = A_BYTES;
static constexpr int B_STAGE    = 16384;                       // 128 rows x 128B (2 sub-chunks)
static constexpr int NSTAGE     = 3;
static constexpr int XSQ_OFF    = B_OFF + NSTAGE * B_STAGE;    // 114688 (64 f)
static constexpr int SMEM_TOTAL = XSQ_OFF + 256;               // 114944
// post-loop aliases into the dead B ring:
static constexpr int PS_OFF     = B_OFF;                       // [64][4] f
static constexpr int RSUM_OFF   = B_OFF + 1024;                // [64] f

__global__ void __launch_bounds__(256, 2)
cluster_main_kernel(const float* __restrict__ x, float* __restrict__ out) {
    extern __shared__ char smem[];
    const uint32_t sb = smem_to_u32(smem);
    const int t  = threadIdx.x;
    const int rowbase = blockIdx.x * 64;

    const int w  = t >> 5;                    // warp id
    const int l  = t & 31;                    // lane
    const int wm = w >> 2;                    // 0..1 (M, 32 rows)
    const int wn = w & 3;                     // 0..3 (N, 32 cols)
    const int group = l >> 2;                 // 0..7
    const int tid4  = l & 3;                  // 0..3

    float* xsq_s  = reinterpret_cast<float*>(smem + XSQ_OFF);

    // ---- B loader (hoisted addressing). idx in [0,64): nt=idx>>3, kcp=idx&7 ----
    const int brow = t >> 2, bch = t & 3;
    const uint32_t bswz0 = swz((uint32_t)brow, (uint32_t)bch);
    const uint32_t bswz1 = swz((uint32_t)(brow + 64), (uint32_t)bch);
    auto load_B = [&](int idx, int slot) {
        const int nt = idx >> 3, kcp = idx & 7;
        const uint32_t s = sb + B_OFF + slot * B_STAGE;
        const __nv_bfloat16* cbT =
            g_cbf + (size_t)(nt * 128) * DDIM + kcp * 64 + bch * 8;
        #pragma unroll
        for (int sub = 0; sub < 2; ++sub) {
            const __nv_bfloat16* gp = cbT + sub * 32;
            CP_ASYNC_16(s + sub * 8192 + bswz0,
                        (uint64_t)__cvta_generic_to_global(gp + (size_t)brow * DDIM));
            CP_ASYNC_16(s + sub * 8192 + bswz1,
                        (uint64_t)__cvta_generic_to_global(gp + (size_t)(brow + 64) * DDIM));
        }
    };

    // prologue: prefetch 2 super-stages, then convert A while they fly
    load_B(0, 0); CP_COMMIT();
    load_B(1, 1); CP_COMMIT();

    // ---- prologue: fp32 x -> bf16 smem A + x_sq (4 threads per row) ----
    {
        const int r  = t >> 2;             // local row 0..63
        const int cb = (t & 3) * 128;      // col base, 128 cols per thread
        const float* xr = x + (size_t)(rowbase + r) * DDIM + cb;
        float s = 0.f;
        #pragma unroll
        for (int i = 0; i < 16; ++i) {
            const int col = cb + i * 8;
            float4 f0 = reinterpret_cast<const float4*>(xr + i * 8)[0];
            float4 f1 = reinterpret_cast<const float4*>(xr + i * 8)[1];
            s += f0.x * f0.x + f0.y * f0.y + f0.z * f0.z + f0.w * f0.w
               + f1.x * f1.x + f1.y * f1.y + f1.z * f1.z + f1.w * f1.w;
            uint32_t p0 = pack_bf2(f0.x, f0.y), p1 = pack_bf2(f0.z, f0.w);
            uint32_t p2 = pack_bf2(f1.x, f1.y), p3 = pack_bf2(f1.z, f1.w);
            const int kc = col >> 5, j = (col & 31) >> 3;
            uint32_t dst = sb + kc * 4096 + swz((uint32_t)r, (uint32_t)j);
            asm volatile("st.shared.v4.b32 [%0], {%1, %2, %3, %4};"
                         :: "r"(dst), "r"(p0), "r"(p1), "r"(p2), "r"(p3));
        }
        s += __shfl_xor_sync(0xFFFFFFFFu, s, 1);
        s += __shfl_xor_sync(0xFFFFFFFFu, s, 2);
        if (tid4 == 0) xsq_s[r] = s;
    }
    __syncthreads();

    // this thread's row squared-norms, in registers for all epilogues
    const int er0 = wm * 32 + group;
    float xs[2][2];
    #pragma unroll
    for (int mi = 0; mi < 2; ++mi) {
        xs[mi][0] = xsq_s[er0 + mi * 16];
        xs[mi][1] = xsq_s[er0 + mi * 16 + 8];
    }

    // ---- ldmatrix lane offsets (relative to 4KB A chunk / 8KB B sub-stage) ----
    uint32_t aAddr[2][2];
    {
        int r8   = (l & 7) + (((l >> 3) & 1) << 3);
        int cbit = l >> 4;
        #pragma unroll
        for (int mi = 0; mi < 2; ++mi) {
            int row = wm * 32 + mi * 16 + r8;
            aAddr[mi][0] = swz(row, cbit);
            aAddr[mi][1] = swz(row, 2 + cbit);
        }
    }
    uint32_t bAddr[2][2];
    {
        int m = l >> 3;
        #pragma unroll
        for (int p = 0; p < 2; ++p) {
            int row = wn * 32 + (p * 2 + (m >> 1)) * 8 + (l & 7);
            #pragma unroll
            for (int ks = 0; ks < 2; ++ks)
                bAddr[p][ks] = swz(row, 2 * ks + (m & 1));
        }
    }

    float acc[2][4][4];
    #pragma unroll
    for (int mi = 0; mi < 2; ++mi)
        #pragma unroll
        for (int nj = 0; nj < 4; ++nj)
            #pragma unroll
            for (int c = 0; c < 4; ++c) acc[mi][nj][c] = 0.f;

    float rs[2][2] = {{0.f, 0.f}, {0.f, 0.f}};   // running row sums

    // ---- 64-iteration pipeline: 8 N-tiles x 8 K-steps of 64 ----
    int cslot = 0;
    #pragma unroll 1
    for (int idx = 0; idx < 64; ++idx) {
        const int kcp = idx & 7;
        // Only stage idx (committed 2 windows ago) must have landed;
        // stages idx+1 / idx+2 stay in flight.
        CP_WAIT_2();
        __syncthreads();
        {
            int lslot = cslot - 1; if (lslot < 0) lslot += 3;  // (cslot+2)%3
            if (idx + 2 < 64) load_B(idx + 2, lslot);
            CP_COMMIT();
        }

        const uint32_t stg = sb + B_OFF + cslot * B_STAGE;
        if (++cslot == 3) cslot = 0;

        #pragma unroll
        for (int half = 0; half < 2; ++half) {
            const uint32_t sA = sb + (kcp * 2 + half) * 4096;
            const uint32_t sB = stg + half * 8192;
            #pragma unroll
            for (int ks = 0; ks < 2; ++ks) {
                uint32_t a[2][4], b[4][2];
                #pragma unroll
                for (int mi = 0; mi < 2; ++mi)
                    LDSM_X4(a[mi][0], a[mi][1], a[mi][2], a[mi][3], sA + aAddr[mi][ks]);
                #pragma unroll
                for (int p = 0; p < 2; ++p)
                    LDSM_X4(b[2*p][0], b[2*p][1], b[2*p+1][0], b[2*p+1][1],
                            sB + bAddr[p][ks]);
                #pragma unroll
                for (int mi = 0; mi < 2; ++mi)
                    #pragma unroll
                    for (int nj = 0; nj < 4; ++nj)
                        MMA_BF16(acc[mi][nj][0], acc[mi][nj][1],
                                 acc[mi][nj][2], acc[mi][nj][3],
                                 a[mi][0], a[mi][1], a[mi][2], a[mi][3],
                                 b[nj][0], b[nj][1]);
            }
        }

        // ---- N-tile epilogue (registers only; csq via __ldg, L2-resident) ----
        if (kcp == 7) {
            const int ntbase = (idx >> 3) * 128;
            #pragma unroll
            for (int mi = 0; mi < 2; ++mi) {
                #pragma unroll
                for (int nj = 0; nj < 4; ++nj) {
                    const int colL = wn * 32 + nj * 8 + tid4 * 2;
                    const float cs0 = __ldg(g_csq + ntbase + colL);
                    const float cs1 = __ldg(g_csq + ntbase + colL + 1);
                    float q00 = __fdividef(1.f, 1.f + fmaxf(xs[mi][0] + cs0 - 2.f * acc[mi][nj][0], 0.f));
                    float q01 = __fdividef(1.f, 1.f + fmaxf(xs[mi][0] + cs1 - 2.f * acc[mi][nj][1], 0.f));
                    float q10 = __fdividef(1.f, 1.f + fmaxf(xs[mi][1] + cs0 - 2.f * acc[mi][nj][2], 0.f));
                    float q11 = __fdividef(1.f, 1.f + fmaxf(xs[mi][1] + cs1 - 2.f * acc[mi][nj][3], 0.f));
                    rs[mi][0] += q00 + q01;
                    rs[mi][1] += q10 + q11;
                    acc[mi][nj][0] = 0.f; acc[mi][nj][1] = 0.f;
                    acc[mi][nj][2] = 0.f; acc[mi][nj][3] = 0.f;
                    const int r0 = wm * 32 + mi * 16 + group;
                    *reinterpret_cast<float2*>(
                        out + (size_t)(rowbase + r0) * KCL + ntbase + colL) = make_float2(q00, q01);
                    *reinterpret_cast<float2*>(
                        out + (size_t)(rowbase + r0 + 8) * KCL + ntbase + colL) = make_float2(q10, q11);
                }
            }
        }
    }

    // ---- final row-sum reduction (ps/rsum alias the dead B ring) ----
    CP_WAIT_0();
    __syncthreads();
    float* ps     = reinterpret_cast<float*>(smem + PS_OFF);   // [64][4]
    float* rsum_s = reinterpret_cast<float*>(smem + RSUM_OFF); // [64]
    #pragma unroll
    for (int mi = 0; mi < 2; ++mi) {
        float s0 = rs[mi][0], s1 = rs[mi][1];
        s0 += __shfl_xor_sync(0xFFFFFFFFu, s0, 1);
        s0 += __shfl_xor_sync(0xFFFFFFFFu, s0, 2);
        s1 += __shfl_xor_sync(0xFFFFFFFFu, s1, 1);
        s1 += __shfl_xor_sync(0xFFFFFFFFu, s1, 2);
        if (tid4 == 0) {
            const int r0 = wm * 32 + mi * 16 + group;
            ps[r0 * 4 + wn] = s0;
            ps[(r0 + 8) * 4 + wn] = s1;
        }
    }
    __syncthreads();
    if (t < 64)
        rsum_s[t] = __fdividef(1.f, ps[t * 4 + 0] + ps[t * 4 + 1] +
                                    ps[t * 4 + 2] + ps[t * 4 + 3]);
    __syncthreads();

    // ---- fused renormalization (256KB output slab, L2-resident) ----
    float4* op = reinterpret_cast<float4*>(out + (size_t)rowbase * KCL);
    #pragma unroll 4
    for (int r = 0; r < 64; ++r) {
        float iv = rsum_s[r];
        float4 v = op[(size_t)r * 256 + t];
        v.x *= iv; v.y *= iv; v.z *= iv; v.w *= iv;
        op[(size_t)r * 256 + t] = v;
    }
}

// ============================ launch =======================================
extern "C" void kernel_launch(void* const* d_in, const int* in_sizes, int n_in,
                              void* d_out, int out_size) {
    const float* x  = (const float*)d_in[0];   // (65536, 512)
    const float* cl = (const float*)d_in[1];   // (1024, 512)
    float* out = (float*)d_out;                // (65536, 1024)
    (void)in_sizes; (void)n_in; (void)out_size;

    cudaFuncSetAttribute(cluster_main_kernel,
                         cudaFuncAttributeMaxDynamicSharedMemorySize, SMEM_TOTAL);

    prep_clusters<<<KCL, 128>>>(cl);
    cluster_main_kernel<<<NROWS / 64, 256, SMEM_TOTAL>>>(x, out);
}

// round 10
// speedup vs baseline: 1.2942x; 1.1617x over previous
#include <cuda_runtime.h>
#include <cuda_bf16.h>
#include <cstdint>

// ============================ problem constants ============================
#define NROWS 65536
#define DDIM  512
#define KCL   1024

// fp8 scaling: x stored as e4m3(8*x), clusters as e4m3(64*c).
// accumulated cross = 512 * (x . c)  ->  2*cross = acc / 256.

// ============================ device scratch ===============================
__device__ uint8_t g_cf8[KCL * DDIM];   // clusters in e4m3*64 (512 KB)
__device__ float g_csq[KCL];            // ||c||^2 (exact fp32)

// ============================ helpers ======================================
__device__ __forceinline__ uint32_t smem_to_u32(const void* p) {
    uint32_t a;
    asm("{ .reg .u64 t; cvta.to.shared.u64 t, %1; cvt.u32.u64 %0, t; }"
        : "=r"(a) : "l"(p));
    return a;
}

// pack 4 floats -> 4 e4m3 bytes (x0 in LSB)
__device__ __forceinline__ uint32_t pack_f8x4(float x0, float x1, float x2, float x3) {
    uint16_t lo, hi;
    asm("cvt.rn.satfinite.e4m3x2.f32 %0, %1, %2;" : "=h"(lo) : "f"(x1), "f"(x0));
    asm("cvt.rn.satfinite.e4m3x2.f32 %0, %1, %2;" : "=h"(hi) : "f"(x3), "f"(x2));
    return (uint32_t)lo | ((uint32_t)hi << 16);
}

// swizzled smem byte offset for (row, 16B-chunk) within a [rows x 64B] tile.
__device__ __forceinline__ uint32_t swz(uint32_t row, uint32_t chunk) {
    return (row << 6) + (((chunk) ^ ((row >> 1) & 3u)) << 4);
}

#define CP_ASYNC_16(saddr, gaddr) \
    asm volatile("cp.async.cg.shared.global [%0], [%1], 16;" \
                 :: "r"(saddr), "l"(gaddr))
#define CP_COMMIT() asm volatile("cp.async.commit_group;" ::: "memory")
#define CP_WAIT_2() asm volatile("cp.async.wait_group 2;" ::: "memory")
#define CP_WAIT_0() asm volatile("cp.async.wait_group 0;" ::: "memory")

#define LDSM_X4(r0, r1, r2, r3, addr) \
    asm volatile("ldmatrix.sync.aligned.m8n8.x4.shared.b16 {%0,%1,%2,%3}, [%4];" \
                 : "=r"(r0), "=r"(r1), "=r"(r2), "=r"(r3) : "r"(addr))

// fp8 e4m3 MMA: m16n8k32, fp32 accum
#define MMA_FP8(d0, d1, d2, d3, a0, a1, a2, a3, b0, b1) \
    asm volatile("mma.sync.aligned.m16n8k32.row.col.f32.e4m3.e4m3.f32 " \
                 "{%0,%1,%2,%3}, {%4,%5,%6,%7}, {%8,%9}, {%0,%1,%2,%3};" \
                 : "+f"(d0), "+f"(d1), "+f"(d2), "+f"(d3) \
                 : "r"(a0), "r"(a1), "r"(a2), "r"(a3), "r"(b0), "r"(b1))

// ============================ prep kernel ==================================
// clusters: fp32 -> e4m3(64*c) + exact ||c||^2
__global__ void prep_clusters(const float* __restrict__ cl) {
    int k = blockIdx.x;
    int t = threadIdx.x;  // 128 threads, one float4 each
    float4 v = reinterpret_cast<const float4*>(cl + (size_t)k * DDIM)[t];
    reinterpret_cast<uint32_t*>(g_cf8 + (size_t)k * DDIM)[t] =
        pack_f8x4(v.x * 64.f, v.y * 64.f, v.z * 64.f, v.w * 64.f);
    float s = v.x * v.x + v.y * v.y + v.z * v.z + v.w * v.w;
    for (int o = 16; o; o >>= 1) s += __shfl_down_sync(0xFFFFFFFFu, s, o);
    __shared__ float ps[4];
    if ((t & 31) == 0) ps[t >> 5] = s;
    __syncthreads();
    if (t == 0) g_csq[k] = ps[0] + ps[1] + ps[2] + ps[3];
}

// ============================ main kernel ==================================
// One CTA per 64-row block, 2 CTAs/SM. A (64x512 fp8, 32KB) smem-resident,
// converted in the prologue with exact fp32 x_sq. 8 N-tiles of 128 cols;
// K-window = 128 fp8 per barrier (2 chunks of 64B, 4 k32 mma steps).
// B via 3-stage x 16KB cp.async ring. Warps 2(M) x 4(N), warp tile 32x32.
// Row sums in registers; ps/rsum alias the dead ring; fused renorm.
static constexpr int A_BYTES    = 64 * 512;                    // 32768
static constexpr int B_OFF      = A_BYTES;
static constexpr int B_STAGE    = 16384;                       // 128 rows x 128B
static constexpr int NSTAGE     = 3;
static constexpr int XSQ_OFF    = B_OFF + NSTAGE * B_STAGE;    // 81920 (64 f)
static constexpr int SMEM_TOTAL = XSQ_OFF + 256;               // 82176
// post-loop aliases into the dead B ring:
static constexpr int PS_OFF     = B_OFF;                       // [64][4] f
static constexpr int RSUM_OFF   = B_OFF + 1024;                // [64] f

__global__ void __launch_bounds__(256, 2)
cluster_main_kernel(const float* __restrict__ x, float* __restrict__ out) {
    extern __shared__ char smem[];
    const uint32_t sb = smem_to_u32(smem);
    const int t  = threadIdx.x;
    const int rowbase = blockIdx.x * 64;

    const int w  = t >> 5;                    // warp id
    const int l  = t & 31;                    // lane
    const int wm = w >> 2;                    // 0..1 (M, 32 rows)
    const int wn = w & 3;                     // 0..3 (N, 32 cols)
    const int group = l >> 2;                 // 0..7
    const int tid4  = l & 3;                  // 0..3

    float* xsq_s = reinterpret_cast<float*>(smem + XSQ_OFF);

    // ---- B loader. idx in [0,32): nt=idx>>2, kcp=idx&3 (128 fp8 of K each) ----
    const int brow = t >> 2, bch = t & 3;
    const uint32_t bswz0 = swz((uint32_t)brow, (uint32_t)bch);
    const uint32_t bswz1 = swz((uint32_t)(brow + 64), (uint32_t)bch);
    auto load_B = [&](int idx, int slot) {
        const int nt = idx >> 2, kcp = idx & 3;
        const uint32_t s = sb + B_OFF + slot * B_STAGE;
        const uint8_t* cbT =
            g_cf8 + (size_t)(nt * 128) * DDIM + kcp * 128 + bch * 16;
        #pragma unroll
        for (int sub = 0; sub < 2; ++sub) {
            const uint8_t* gp = cbT + sub * 64;
            CP_ASYNC_16(s + sub * 8192 + bswz0,
                        (uint64_t)__cvta_generic_to_global(gp + (size_t)brow * DDIM));
            CP_ASYNC_16(s + sub * 8192 + bswz1,
                        (uint64_t)__cvta_generic_to_global(gp + (size_t)(brow + 64) * DDIM));
        }
    };

    // prologue: prefetch 2 stages, then convert A while they fly
    load_B(0, 0); CP_COMMIT();
    load_B(1, 1); CP_COMMIT();

    // ---- prologue: fp32 x -> e4m3(8x) smem A + exact x_sq (4 thr/row) ----
    {
        const int r  = t >> 2;             // local row 0..63
        const int cb = (t & 3) * 128;      // fp8-col base, 128 cols per thread
        const float* xr = x + (size_t)(rowbase + r) * DDIM + cb;
        float s = 0.f;
        #pragma unroll
        for (int i = 0; i < 8; ++i) {
            const int col = cb + i * 16;
            float4 f0 = reinterpret_cast<const float4*>(xr + i * 16)[0];
            float4 f1 = reinterpret_cast<const float4*>(xr + i * 16)[1];
            float4 f2 = reinterpret_cast<const float4*>(xr + i * 16)[2];
            float4 f3 = reinterpret_cast<const float4*>(xr + i * 16)[3];
            s += f0.x * f0.x + f0.y * f0.y + f0.z * f0.z + f0.w * f0.w
               + f1.x * f1.x + f1.y * f1.y + f1.z * f1.z + f1.w * f1.w
               + f2.x * f2.x + f2.y * f2.y + f2.z * f2.z + f2.w * f2.w
               + f3.x * f3.x + f3.y * f3.y + f3.z * f3.z + f3.w * f3.w;
            uint32_t p0 = pack_f8x4(f0.x * 8.f, f0.y * 8.f, f0.z * 8.f, f0.w * 8.f);
            uint32_t p1 = pack_f8x4(f1.x * 8.f, f1.y * 8.f, f1.z * 8.f, f1.w * 8.f);
            uint32_t p2 = pack_f8x4(f2.x * 8.f, f2.y * 8.f, f2.z * 8.f, f2.w * 8.f);
            uint32_t p3 = pack_f8x4(f3.x * 8.f, f3.y * 8.f, f3.z * 8.f, f3.w * 8.f);
            const int kc = col >> 6, j = (col & 63) >> 4;
            uint32_t dst = sb + kc * 4096 + swz((uint32_t)r, (uint32_t)j);
            asm volatile("st.shared.v4.b32 [%0], {%1, %2, %3, %4};"
                         :: "r"(dst), "r"(p0), "r"(p1), "r"(p2), "r"(p3));
        }
        s += __shfl_xor_sync(0xFFFFFFFFu, s, 1);
        s += __shfl_xor_sync(0xFFFFFFFFu, s, 2);
        if (tid4 == 0) xsq_s[r] = s;
    }
    __syncthreads();

    // this thread's row squared-norms, in registers for all epilogues
    const int er0 = wm * 32 + group;
    float xs[2][2];
    #pragma unroll
    for (int mi = 0; mi < 2; ++mi) {
        xs[mi][0] = xsq_s[er0 + mi * 16];
        xs[mi][1] = xsq_s[er0 + mi * 16 + 8];
    }

    // ---- ldmatrix lane offsets (byte geometry within 64B-row chunks) ----
    uint32_t aAddr[2][2];
    {
        int r8   = (l & 7) + (((l >> 3) & 1) << 3);
        int cbit = l >> 4;
        #pragma unroll
        for (int mi = 0; mi < 2; ++mi) {
            int row = wm * 32 + mi * 16 + r8;
            aAddr[mi][0] = swz(row, cbit);
            aAddr[mi][1] = swz(row, 2 + cbit);
        }
    }
    uint32_t bAddr[2][2];
    {
        int m = l >> 3;
        #pragma unroll
        for (int p = 0; p < 2; ++p) {
            int row = wn * 32 + (p * 2 + (m >> 1)) * 8 + (l & 7);
            #pragma unroll
            for (int ks = 0; ks < 2; ++ks)
                bAddr[p][ks] = swz(row, 2 * ks + (m & 1));
        }
    }

    float acc[2][4][4];
    #pragma unroll
    for (int mi = 0; mi < 2; ++mi)
        #pragma unroll
        for (int nj = 0; nj < 4; ++nj)
            #pragma unroll
            for (int c = 0; c < 4; ++c) acc[mi][nj][c] = 0.f;

    float rs[2][2] = {{0.f, 0.f}, {0.f, 0.f}};   // running row sums

    // ---- 32-iteration pipeline: 8 N-tiles x 4 K-windows of 128 ----
    int cslot = 0;
    #pragma unroll 1
    for (int idx = 0; idx < 32; ++idx) {
        const int kcp = idx & 3;
        CP_WAIT_2();
        __syncthreads();
        {
            int lslot = cslot - 1; if (lslot < 0) lslot += 3;  // (cslot+2)%3
            if (idx + 2 < 32) load_B(idx + 2, lslot);
            CP_COMMIT();
        }

        const uint32_t stg = sb + B_OFF + cslot * B_STAGE;
        if (++cslot == 3) cslot = 0;

        #pragma unroll
        for (int half = 0; half < 2; ++half) {
            const uint32_t sA = sb + (kcp * 2 + half) * 4096;
            const uint32_t sB = stg + half * 8192;
            #pragma unroll
            for (int ks = 0; ks < 2; ++ks) {
                uint32_t a[2][4], b[4][2];
                #pragma unroll
                for (int mi = 0; mi < 2; ++mi)
                    LDSM_X4(a[mi][0], a[mi][1], a[mi][2], a[mi][3], sA + aAddr[mi][ks]);
                #pragma unroll
                for (int p = 0; p < 2; ++p)
                    LDSM_X4(b[2*p][0], b[2*p][1], b[2*p+1][0], b[2*p+1][1],
                            sB + bAddr[p][ks]);
                #pragma unroll
                for (int mi = 0; mi < 2; ++mi)
                    #pragma unroll
                    for (int nj = 0; nj < 4; ++nj)
                        MMA_FP8(acc[mi][nj][0], acc[mi][nj][1],
                                acc[mi][nj][2], acc[mi][nj][3],
                                a[mi][0], a[mi][1], a[mi][2], a[mi][3],
                                b[nj][0], b[nj][1]);
            }
        }

        // ---- N-tile epilogue (registers only; csq via __ldg, L2-resident) ----
        if (kcp == 3) {
            const int ntbase = (idx >> 2) * 128;
            const float kk = 1.f / 256.f;   // 2*cross = acc/256
            #pragma unroll
            for (int mi = 0; mi < 2; ++mi) {
                #pragma unroll
                for (int nj = 0; nj < 4; ++nj) {
                    const int colL = wn * 32 + nj * 8 + tid4 * 2;
                    const float cs0 = __ldg(g_csq + ntbase + colL);
                    const float cs1 = __ldg(g_csq + ntbase + colL + 1);
                    float q00 = __fdividef(1.f, 1.f + fmaxf(xs[mi][0] + cs0 - kk * acc[mi][nj][0], 0.f));
                    float q01 = __fdividef(1.f, 1.f + fmaxf(xs[mi][0] + cs1 - kk * acc[mi][nj][1], 0.f));
                    float q10 = __fdividef(1.f, 1.f + fmaxf(xs[mi][1] + cs0 - kk * acc[mi][nj][2], 0.f));
                    float q11 = __fdividef(1.f, 1.f + fmaxf(xs[mi][1] + cs1 - kk * acc[mi][nj][3], 0.f));
                    rs[mi][0] += q00 + q01;
                    rs[mi][1] += q10 + q11;
                    acc[mi][nj][0] = 0.f; acc[mi][nj][1] = 0.f;
                    acc[mi][nj][2] = 0.f; acc[mi][nj][3] = 0.f;
                    const int r0 = wm * 32 + mi * 16 + group;
                    *reinterpret_cast<float2*>(
                        out + (size_t)(rowbase + r0) * KCL + ntbase + colL) = make_float2(q00, q01);
                    *reinterpret_cast<float2*>(
                        out + (size_t)(rowbase + r0 + 8) * KCL + ntbase + colL) = make_float2(q10, q11);
                }
            }
        }
    }

    // ---- final row-sum reduction (ps/rsum alias the dead B ring) ----
    CP_WAIT_0();
    __syncthreads();
    float* ps     = reinterpret_cast<float*>(smem + PS_OFF);   // [64][4]
    float* rsum_s = reinterpret_cast<float*>(smem + RSUM_OFF); // [64]
    #pragma unroll
    for (int mi = 0; mi < 2; ++mi) {
        float s0 = rs[mi][0], s1 = rs[mi][1];
        s0 += __shfl_xor_sync(0xFFFFFFFFu, s0, 1);
        s0 += __shfl_xor_sync(0xFFFFFFFFu, s0, 2);
        s1 += __shfl_xor_sync(0xFFFFFFFFu, s1, 1);
        s1 += __shfl_xor_sync(0xFFFFFFFFu, s1, 2);
        if (tid4 == 0) {
            const int r0 = wm * 32 + mi * 16 + group;
            ps[r0 * 4 + wn] = s0;
            ps[(r0 + 8) * 4 + wn] = s1;
        }
    }
    __syncthreads();
    if (t < 64)
        rsum_s[t] = __fdividef(1.f, ps[t * 4 + 0] + ps[t * 4 + 1] +
                                    ps[t * 4 + 2] + ps[t * 4 + 3]);
    __syncthreads();

    // ---- fused renormalization (256KB output slab, L2-resident) ----
    float4* op = reinterpret_cast<float4*>(out + (size_t)rowbase * KCL);
    #pragma unroll 4
    for (int r = 0; r < 64; ++r) {
        float iv = rsum_s[r];
        float4 v = op[(size_t)r * 256 + t];
        v.x *= iv; v.y *= iv; v.z *= iv; v.w *= iv;
        op[(size_t)r * 256 + t] = v;
    }
}

// ============================ launch =======================================
extern "C" void kernel_launch(void* const* d_in, const int* in_sizes, int n_in,
                              void* d_out, int out_size) {
    const float* x  = (const float*)d_in[0];   // (65536, 512)
    const float* cl = (const float*)d_in[1];   // (1024, 512)
    float* out = (float*)d_out;                // (65536, 1024)
    (void)in_sizes; (void)n_in; (void)out_size;

    cudaFuncSetAttribute(cluster_main_kernel,
                         cudaFuncAttributeMaxDynamicSharedMemorySize, SMEM_TOTAL);

    prep_clusters<<<KCL, 128>>>(cl);
    cluster_main_kernel<<<NROWS / 64, 256, SMEM_TOTAL>>>(x, out);
}

// round 11
// speedup vs baseline: 1.3193x; 1.0194x over previous
#include <cuda_runtime.h>
#include <cuda_bf16.h>
#include <cstdint>

// ============================ problem constants ============================
#define NROWS 65536
#define DDIM  512
#define KCL   1024

// fp8 scaling: x stored as e4m3(8*x), clusters as e4m3(64*c).
// accumulated cross = 512 * (x . c)  ->  2*cross = acc / 256.

// ============================ device scratch ===============================
__device__ uint8_t g_cf8[KCL * DDIM];          // clusters e4m3*64, row-major
// B pre-swizzled stage images: 32 blocks (nt*4+kcp) x 16384 bytes, each an
// exact smem-stage byte image (sub-chunk + SW swizzle baked in).
__device__ uint8_t g_breord[32 * 16384];
__device__ float g_csq[KCL];                   // ||c||^2 (exact fp32)

// ============================ helpers ======================================
__device__ __forceinline__ uint32_t smem_to_u32(const void* p) {
    uint32_t a;
    asm("{ .reg .u64 t; cvta.to.shared.u64 t, %1; cvt.u32.u64 %0, t; }"
        : "=r"(a) : "l"(p));
    return a;
}

// pack 4 floats -> 4 e4m3 bytes (x0 in LSB)
__device__ __forceinline__ uint32_t pack_f8x4(float x0, float x1, float x2, float x3) {
    uint16_t lo, hi;
    asm("cvt.rn.satfinite.e4m3x2.f32 %0, %1, %2;" : "=h"(lo) : "f"(x1), "f"(x0));
    asm("cvt.rn.satfinite.e4m3x2.f32 %0, %1, %2;" : "=h"(hi) : "f"(x3), "f"(x2));
    return (uint32_t)lo | ((uint32_t)hi << 16);
}

// swizzled smem byte offset for (row, 16B-chunk) within a [rows x 64B] tile.
__device__ __forceinline__ uint32_t swz(uint32_t row, uint32_t chunk) {
    return (row << 6) + (((chunk) ^ ((row >> 1) & 3u)) << 4);
}

#define CP_ASYNC_16(saddr, gaddr) \
    asm volatile("cp.async.cg.shared.global [%0], [%1], 16;" \
                 :: "r"(saddr), "l"(gaddr))
#define CP_COMMIT() asm volatile("cp.async.commit_group;" ::: "memory")
#define CP_WAIT_2() asm volatile("cp.async.wait_group 2;" ::: "memory")
#define CP_WAIT_0() asm volatile("cp.async.wait_group 0;" ::: "memory")

#define LDSM_X4(r0, r1, r2, r3, addr) \
    asm volatile("ldmatrix.sync.aligned.m8n8.x4.shared.b16 {%0,%1,%2,%3}, [%4];" \
                 : "=r"(r0), "=r"(r1), "=r"(r2), "=r"(r3) : "r"(addr))

// fp8 e4m3 MMA: m16n8k32, fp32 accum
#define MMA_FP8(d0, d1, d2, d3, a0, a1, a2, a3, b0, b1) \
    asm volatile("mma.sync.aligned.m16n8k32.row.col.f32.e4m3.e4m3.f32 " \
                 "{%0,%1,%2,%3}, {%4,%5,%6,%7}, {%8,%9}, {%0,%1,%2,%3};" \
                 : "+f"(d0), "+f"(d1), "+f"(d2), "+f"(d3) \
                 : "r"(a0), "r"(a1), "r"(a2), "r"(a3), "r"(b0), "r"(b1))

// ============================ prep kernels =================================
// clusters: fp32 -> e4m3(64*c) row-major + exact ||c||^2
__global__ void prep_clusters(const float* __restrict__ cl) {
    int k = blockIdx.x;
    int t = threadIdx.x;  // 128 threads, one float4 each
    float4 v = reinterpret_cast<const float4*>(cl + (size_t)k * DDIM)[t];
    reinterpret_cast<uint32_t*>(g_cf8 + (size_t)k * DDIM)[t] =
        pack_f8x4(v.x * 64.f, v.y * 64.f, v.z * 64.f, v.w * 64.f);
    float s = v.x * v.x + v.y * v.y + v.z * v.z + v.w * v.w;
    for (int o = 16; o; o >>= 1) s += __shfl_down_sync(0xFFFFFFFFu, s, o);
    __shared__ float ps[4];
    if ((t & 31) == 0) ps[t >> 5] = s;
    __syncthreads();
    if (t == 0) g_csq[k] = ps[0] + ps[1] + ps[2] + ps[3];
}

// reorder g_cf8 into pre-swizzled stage images.
// grid 1024 (cluster row n), 128 threads (16B chunk of its 512 fp8 bytes? ->
// each thread handles one uint32 = 4 bytes; 128 thr x 4B = 512 B per row).
__global__ void prep_breord() {
    const int n = blockIdx.x;          // cluster row 0..1023
    const int t = threadIdx.x;         // 0..127, 4 fp8 cols each
    const int col = t * 4;             // k index of first byte
    const int nt  = n >> 7;            // n / 128
    const int r   = n & 127;           // row within tile
    const int kcp = col >> 7;          // 128-k window within row
    const int s   = (col & 127) >> 6;  // 64B sub-chunk
    const int ch  = (col & 63) >> 4;   // 16B chunk
    const int b   = col & 15;          // byte within chunk
    uint32_t v = reinterpret_cast<const uint32_t*>(g_cf8 + (size_t)n * DDIM)[t];
    uint8_t* dst = g_breord + (size_t)(nt * 4 + kcp) * 16384
                 + s * 8192 + swz((uint32_t)r, (uint32_t)ch) + b;
    *reinterpret_cast<uint32_t*>(dst) = v;
}

// ============================ main kernel ==================================
// One CTA per 64-row block, 2 CTAs/SM. A (64x512 fp8, 32KB) smem-resident.
// 8 N-tiles of 128 cols; K-window = 128 fp8 per barrier (4 k32 mma steps).
// B via 4-stage x 16KB ring of pre-swizzled LINEAR copies; ring period 4 ==
// epilogue period, so all slot indices are compile-time under unroll-4.
static constexpr int A_BYTES    = 64 * 512;                    // 32768
static constexpr int B_OFF      = A_BYTES;
static constexpr int B_STAGE    = 16384;
static constexpr int NSTAGE     = 4;
static constexpr int XSQ_OFF    = B_OFF + NSTAGE * B_STAGE;    // 98304 (64 f)
static constexpr int SMEM_TOTAL = XSQ_OFF + 256;               // 98560
// post-loop aliases into the dead B ring:
static constexpr int PS_OFF     = B_OFF;                       // [64][4] f
static constexpr int RSUM_OFF   = B_OFF + 1024;                // [64] f

__global__ void __launch_bounds__(256, 2)
cluster_main_kernel(const float* __restrict__ x, float* __restrict__ out) {
    extern __shared__ char smem[];
    const uint32_t sb = smem_to_u32(smem);
    const int t  = threadIdx.x;
    const int rowbase = blockIdx.x * 64;

    const int w  = t >> 5;                    // warp id
    const int l  = t & 31;                    // lane
    const int wm = w >> 2;                    // 0..1 (M, 32 rows)
    const int wn = w & 3;                     // 0..3 (N, 32 cols)
    const int group = l >> 2;                 // 0..7
    const int tid4  = l & 3;                  // 0..3

    float* xsq_s = reinterpret_cast<float*>(smem + XSQ_OFF);

    // ---- B loader: 4 linear 16B cp.asyncs (stage image copy) ----
    const uint32_t bdst = sb + B_OFF + t * 16;
    auto load_B = [&](int idx, int slot) {
        const uint8_t* gp = g_breord + (size_t)idx * 16384 + t * 16;
        const uint32_t s = bdst + slot * B_STAGE;
        CP_ASYNC_16(s,         (uint64_t)__cvta_generic_to_global(gp));
        CP_ASYNC_16(s + 4096,  (uint64_t)__cvta_generic_to_global(gp + 4096));
        CP_ASYNC_16(s + 8192,  (uint64_t)__cvta_generic_to_global(gp + 8192));
        CP_ASYNC_16(s + 12288, (uint64_t)__cvta_generic_to_global(gp + 12288));
    };

    // prologue: prefetch 3 stages, then convert A while they fly
    load_B(0, 0); CP_COMMIT();
    load_B(1, 1); CP_COMMIT();
    load_B(2, 2); CP_COMMIT();

    // ---- prologue: fp32 x -> e4m3(8x) smem A + exact x_sq (4 thr/row) ----
    {
        const int r  = t >> 2;             // local row 0..63
        const int cb = (t & 3) * 128;      // fp8-col base, 128 cols per thread
        const float* xr = x + (size_t)(rowbase + r) * DDIM + cb;
        float s = 0.f;
        #pragma unroll
        for (int i = 0; i < 8; ++i) {
            const int col = cb + i * 16;
            float4 f0 = reinterpret_cast<const float4*>(xr + i * 16)[0];
            float4 f1 = reinterpret_cast<const float4*>(xr + i * 16)[1];
            float4 f2 = reinterpret_cast<const float4*>(xr + i * 16)[2];
            float4 f3 = reinterpret_cast<const float4*>(xr + i * 16)[3];
            s += f0.x * f0.x + f0.y * f0.y + f0.z * f0.z + f0.w * f0.w
               + f1.x * f1.x + f1.y * f1.y + f1.z * f1.z + f1.w * f1.w
               + f2.x * f2.x + f2.y * f2.y + f2.z * f2.z + f2.w * f2.w
               + f3.x * f3.x + f3.y * f3.y + f3.z * f3.z + f3.w * f3.w;
            uint32_t p0 = pack_f8x4(f0.x * 8.f, f0.y * 8.f, f0.z * 8.f, f0.w * 8.f);
            uint32_t p1 = pack_f8x4(f1.x * 8.f, f1.y * 8.f, f1.z * 8.f, f1.w * 8.f);
            uint32_t p2 = pack_f8x4(f2.x * 8.f, f2.y * 8.f, f2.z * 8.f, f2.w * 8.f);
            uint32_t p3 = pack_f8x4(f3.x * 8.f, f3.y * 8.f, f3.z * 8.f, f3.w * 8.f);
            const int kc = col >> 6, j = (col & 63) >> 4;
            uint32_t dst = sb + kc * 4096 + swz((uint32_t)r, (uint32_t)j);
            asm volatile("st.shared.v4.b32 [%0], {%1, %2, %3, %4};"
                         :: "r"(dst), "r"(p0), "r"(p1), "r"(p2), "r"(p3));
        }
        s += __shfl_xor_sync(0xFFFFFFFFu, s, 1);
        s += __shfl_xor_sync(0xFFFFFFFFu, s, 2);
        if (tid4 == 0) xsq_s[r] = s;
    }
    __syncthreads();

    // this thread's row squared-norms, in registers for all epilogues
    const int er0 = wm * 32 + group;
    float xs[2][2];
    #pragma unroll
    for (int mi = 0; mi < 2; ++mi) {
        xs[mi][0] = xsq_s[er0 + mi * 16];
        xs[mi][1] = xsq_s[er0 + mi * 16 + 8];
    }

    // ---- ldmatrix lane offsets ----
    uint32_t aAddr[2][2];
    {
        int r8   = (l & 7) + (((l >> 3) & 1) << 3);
        int cbit = l >> 4;
        #pragma unroll
        for (int mi = 0; mi < 2; ++mi) {
            int row = wm * 32 + mi * 16 + r8;
            aAddr[mi][0] = swz(row, cbit);
            aAddr[mi][1] = swz(row, 2 + cbit);
        }
    }
    uint32_t bAddr[2][2];
    {
        int m = l >> 3;
        #pragma unroll
        for (int p = 0; p < 2; ++p) {
            int row = wn * 32 + (p * 2 + (m >> 1)) * 8 + (l & 7);
            #pragma unroll
            for (int ks = 0; ks < 2; ++ks)
                bAddr[p][ks] = swz(row, 2 * ks + (m & 1));
        }
    }

    float acc[2][4][4];
    #pragma unroll
    for (int mi = 0; mi < 2; ++mi)
        #pragma unroll
        for (int nj = 0; nj < 4; ++nj)
            #pragma unroll
            for (int c = 0; c < 4; ++c) acc[mi][nj][c] = 0.f;

    float rs[2][2] = {{0.f, 0.f}, {0.f, 0.f}};   // running row sums

    // precomputed output row pointers
    float* outp[2][2];
    #pragma unroll
    for (int mi = 0; mi < 2; ++mi) {
        const int r0 = wm * 32 + mi * 16 + group;
        outp[mi][0] = out + (size_t)(rowbase + r0) * KCL;
        outp[mi][1] = out + (size_t)(rowbase + r0 + 8) * KCL;
    }

    // ---- 8 N-tiles x 4 K-windows; slot == kcp (compile-time) ----
    #pragma unroll 1
    for (int nt = 0; nt < 8; ++nt) {
        #pragma unroll
        for (int kcp = 0; kcp < 4; ++kcp) {
            const int idx = nt * 4 + kcp;
            CP_WAIT_2();
            __syncthreads();
            if (idx + 3 < 32) load_B(idx + 3, (kcp + 3) & 3);
            CP_COMMIT();

            const uint32_t stg = sb + B_OFF + kcp * B_STAGE;
            #pragma unroll
            for (int half = 0; half < 2; ++half) {
                const uint32_t sA = sb + (kcp * 2 + half) * 4096;
                const uint32_t sB = stg + half * 8192;
                #pragma unroll
                for (int ks = 0; ks < 2; ++ks) {
                    uint32_t a[2][4], b[4][2];
                    #pragma unroll
                    for (int mi = 0; mi < 2; ++mi)
                        LDSM_X4(a[mi][0], a[mi][1], a[mi][2], a[mi][3], sA + aAddr[mi][ks]);
                    #pragma unroll
                    for (int p = 0; p < 2; ++p)
                        LDSM_X4(b[2*p][0], b[2*p][1], b[2*p+1][0], b[2*p+1][1],
                                sB + bAddr[p][ks]);
                    #pragma unroll
                    for (int mi = 0; mi < 2; ++mi)
                        #pragma unroll
                        for (int nj = 0; nj < 4; ++nj)
                            MMA_FP8(acc[mi][nj][0], acc[mi][nj][1],
                                    acc[mi][nj][2], acc[mi][nj][3],
                                    a[mi][0], a[mi][1], a[mi][2], a[mi][3],
                                    b[nj][0], b[nj][1]);
                }
            }
        }

        // ---- N-tile epilogue (registers only; csq via __ldg, L2-resident) ----
        {
            const int ntbase = nt * 128;
            const float kk = 1.f / 256.f;   // 2*cross = acc/256
            #pragma unroll
            for (int mi = 0; mi < 2; ++mi) {
                #pragma unroll
                for (int nj = 0; nj < 4; ++nj) {
                    const int colg = ntbase + wn * 32 + nj * 8 + tid4 * 2;
                    const float cs0 = __ldg(g_csq + colg);
                    const float cs1 = __ldg(g_csq + colg + 1);
                    float q00 = __fdividef(1.f, 1.f + fmaxf(xs[mi][0] + cs0 - kk * acc[mi][nj][0], 0.f));
                    float q01 = __fdividef(1.f, 1.f + fmaxf(xs[mi][0] + cs1 - kk * acc[mi][nj][1], 0.f));
                    float q10 = __fdividef(1.f, 1.f + fmaxf(xs[mi][1] + cs0 - kk * acc[mi][nj][2], 0.f));
                    float q11 = __fdividef(1.f, 1.f + fmaxf(xs[mi][1] + cs1 - kk * acc[mi][nj][3], 0.f));
                    rs[mi][0] += q00 + q01;
                    rs[mi][1] += q10 + q11;
                    acc[mi][nj][0] = 0.f; acc[mi][nj][1] = 0.f;
                    acc[mi][nj][2] = 0.f; acc[mi][nj][3] = 0.f;
                    *reinterpret_cast<float2*>(outp[mi][0] + colg) = make_float2(q00, q01);
                    *reinterpret_cast<float2*>(outp[mi][1] + colg) = make_float2(q10, q11);
                }
            }
        }
    }

    // ---- final row-sum reduction (ps/rsum alias the dead B ring) ----
    CP_WAIT_0();
    __syncthreads();
    float* ps     = reinterpret_cast<float*>(smem + PS_OFF);   // [64][4]
    float* rsum_s = reinterpret_cast<float*>(smem + RSUM_OFF); // [64]
    #pragma unroll
    for (int mi = 0; mi < 2; ++mi) {
        float s0 = rs[mi][0], s1 = rs[mi][1];
        s0 += __shfl_xor_sync(0xFFFFFFFFu, s0, 1);
        s0 += __shfl_xor_sync(0xFFFFFFFFu, s0, 2);
        s1 += __shfl_xor_sync(0xFFFFFFFFu, s1, 1);
        s1 += __shfl_xor_sync(0xFFFFFFFFu, s1, 2);
        if (tid4 == 0) {
            const int r0 = wm * 32 + mi * 16 + group;
            ps[r0 * 4 + wn] = s0;
            ps[(r0 + 8) * 4 + wn] = s1;
        }
    }
    __syncthreads();
    if (t < 64)
        rsum_s[t] = __fdividef(1.f, ps[t * 4 + 0] + ps[t * 4 + 1] +
                                    ps[t * 4 + 2] + ps[t * 4 + 3]);
    __syncthreads();

    // ---- fused renormalization (256KB output slab, L2-resident) ----
    float4* op = reinterpret_cast<float4*>(out + (size_t)rowbase * KCL);
    #pragma unroll 4
    for (int r = 0; r < 64; ++r) {
        float iv = rsum_s[r];
        float4 v = op[(size_t)r * 256 + t];
        v.x *= iv; v.y *= iv; v.z *= iv; v.w *= iv;
        op[(size_t)r * 256 + t] = v;
    }
}

// ============================ launch =======================================
extern "C" void kernel_launch(void* const* d_in, const int* in_sizes, int n_in,
                              void* d_out, int out_size) {
    const float* x  = (const float*)d_in[0];   // (65536, 512)
    const float* cl = (const float*)d_in[1];   // (1024, 512)
    float* out = (float*)d_out;                // (65536, 1024)
    (void)in_sizes; (void)n_in; (void)out_size;

    cudaFuncSetAttribute(cluster_main_kernel,
                         cudaFuncAttributeMaxDynamicSharedMemorySize, SMEM_TOTAL);

    prep_clusters<<<KCL, 128>>>(cl);
    prep_breord<<<KCL, 128>>>();
    cluster_main_kernel<<<NROWS / 64, 256, SMEM_TOTAL>>>(x, out);
}

// round 12
// speedup vs baseline: 1.3537x; 1.0261x over previous
#include <cuda_runtime.h>
#include <cuda_bf16.h>
#include <cuda_fp16.h>
#include <cstdint>

// ============================ problem constants ============================
#define NROWS 65536
#define DDIM  512
#define KCL   1024

// fp8 scaling: x stored as e4m3(8*x), clusters as e4m3(64*c).
// accumulated cross = 512 * (x . c)  ->  2*cross = acc / 256.

// ============================ device scratch ===============================
__device__ uint8_t g_cf8[KCL * DDIM];          // clusters e4m3*64, row-major
// B pre-swizzled stage images: 32 blocks (nt*4+kcp) x 16384 bytes.
__device__ uint8_t g_breord[32 * 16384];
__device__ float g_csq[KCL];                   // ||c||^2 (exact fp32)

// ============================ helpers ======================================
__device__ __forceinline__ uint32_t smem_to_u32(const void* p) {
    uint32_t a;
    asm("{ .reg .u64 t; cvta.to.shared.u64 t, %1; cvt.u32.u64 %0, t; }"
        : "=r"(a) : "l"(p));
    return a;
}

// pack 4 floats -> 4 e4m3 bytes (x0 in LSB)
__device__ __forceinline__ uint32_t pack_f8x4(float x0, float x1, float x2, float x3) {
    uint16_t lo, hi;
    asm("cvt.rn.satfinite.e4m3x2.f32 %0, %1, %2;" : "=h"(lo) : "f"(x1), "f"(x0));
    asm("cvt.rn.satfinite.e4m3x2.f32 %0, %1, %2;" : "=h"(hi) : "f"(x3), "f"(x2));
    return (uint32_t)lo | ((uint32_t)hi << 16);
}

// swizzled smem byte offset for (row, 16B-chunk) within a [rows x 64B] tile.
__device__ __forceinline__ uint32_t swz(uint32_t row, uint32_t chunk) {
    return (row << 6) + (((chunk) ^ ((row >> 1) & 3u)) << 4);
}

#define CP_ASYNC_16(saddr, gaddr) \
    asm volatile("cp.async.cg.shared.global [%0], [%1], 16;" \
                 :: "r"(saddr), "l"(gaddr))
#define CP_COMMIT() asm volatile("cp.async.commit_group;" ::: "memory")
#define CP_WAIT_2() asm volatile("cp.async.wait_group 2;" ::: "memory")
#define CP_WAIT_0() asm volatile("cp.async.wait_group 0;" ::: "memory")

#define LDSM_X4(r0, r1, r2, r3, addr) \
    asm volatile("ldmatrix.sync.aligned.m8n8.x4.shared.b16 {%0,%1,%2,%3}, [%4];" \
                 : "=r"(r0), "=r"(r1), "=r"(r2), "=r"(r3) : "r"(addr))

// fp8 e4m3 MMA: m16n8k32, FP16 accumulate (2 regs per fragment)
#define MMA_FP8H(d0, d1, a0, a1, a2, a3, b0, b1) \
    asm volatile("mma.sync.aligned.m16n8k32.row.col.f16.e4m3.e4m3.f16 " \
                 "{%0,%1}, {%2,%3,%4,%5}, {%6,%7}, {%0,%1};" \
                 : "+r"(d0), "+r"(d1) \
                 : "r"(a0), "r"(a1), "r"(a2), "r"(a3), "r"(b0), "r"(b1))

// ============================ prep kernels =================================
__global__ void prep_clusters(const float* __restrict__ cl) {
    int k = blockIdx.x;
    int t = threadIdx.x;  // 128 threads, one float4 each
    float4 v = reinterpret_cast<const float4*>(cl + (size_t)k * DDIM)[t];
    reinterpret_cast<uint32_t*>(g_cf8 + (size_t)k * DDIM)[t] =
        pack_f8x4(v.x * 64.f, v.y * 64.f, v.z * 64.f, v.w * 64.f);
    float s = v.x * v.x + v.y * v.y + v.z * v.z + v.w * v.w;
    for (int o = 16; o; o >>= 1) s += __shfl_down_sync(0xFFFFFFFFu, s, o);
    __shared__ float ps[4];
    if ((t & 31) == 0) ps[t >> 5] = s;
    __syncthreads();
    if (t == 0) g_csq[k] = ps[0] + ps[1] + ps[2] + ps[3];
}

// reorder g_cf8 into pre-swizzled stage images (one uint32 per thread).
__global__ void prep_breord() {
    const int n = blockIdx.x;          // cluster row 0..1023
    const int t = threadIdx.x;         // 0..127, 4 fp8 cols each
    const int col = t * 4;
    const int nt  = n >> 7;
    const int r   = n & 127;
    const int kcp = col >> 7;
    const int s   = (col & 127) >> 6;
    const int ch  = (col & 63) >> 4;
    const int b   = col & 15;
    uint32_t v = reinterpret_cast<const uint32_t*>(g_cf8 + (size_t)n * DDIM)[t];
    uint8_t* dst = g_breord + (size_t)(nt * 4 + kcp) * 16384
                 + s * 8192 + swz((uint32_t)r, (uint32_t)ch) + b;
    *reinterpret_cast<uint32_t*>(dst) = v;
}

// ============================ main kernel ==================================
// One CTA per 64-row block, 2 CTAs/SM. A (64x512 fp8, 32KB) smem-resident.
// 8 N-tiles of 128 cols; K-window = 128 fp8 (4 k32 mma steps, f16 accum).
// B via 4-stage x 16KB ring of pre-swizzled LINEAR copies (slot==kcp).
static constexpr int A_BYTES    = 64 * 512;                    // 32768
static constexpr int B_OFF      = A_BYTES;
static constexpr int B_STAGE    = 16384;
static constexpr int NSTAGE     = 4;
static constexpr int XSQ_OFF    = B_OFF + NSTAGE * B_STAGE;    // 98304 (64 f)
static constexpr int SMEM_TOTAL = XSQ_OFF + 256;               // 98560
// post-loop aliases into the dead B ring:
static constexpr int PS_OFF     = B_OFF;                       // [64][4] f
static constexpr int RSUM_OFF   = B_OFF + 1024;                // [64] f

__global__ void __launch_bounds__(256, 2)
cluster_main_kernel(const float* __restrict__ x, float* __restrict__ out) {
    extern __shared__ char smem[];
    const uint32_t sb = smem_to_u32(smem);
    const int t  = threadIdx.x;
    const int rowbase = blockIdx.x * 64;

    const int w  = t >> 5;                    // warp id
    const int l  = t & 31;                    // lane
    const int wm = w >> 2;                    // 0..1 (M, 32 rows)
    const int wn = w & 3;                     // 0..3 (N, 32 cols)
    const int group = l >> 2;                 // 0..7
    const int tid4  = l & 3;                  // 0..3

    float* xsq_s = reinterpret_cast<float*>(smem + XSQ_OFF);

    // ---- B loader: 4 linear 16B cp.asyncs (stage image copy) ----
    const uint32_t bdst = sb + B_OFF + t * 16;
    auto load_B = [&](int idx, int slot) {
        const uint8_t* gp = g_breord + (size_t)idx * 16384 + t * 16;
        const uint32_t s = bdst + slot * B_STAGE;
        CP_ASYNC_16(s,         (uint64_t)__cvta_generic_to_global(gp));
        CP_ASYNC_16(s + 4096,  (uint64_t)__cvta_generic_to_global(gp + 4096));
        CP_ASYNC_16(s + 8192,  (uint64_t)__cvta_generic_to_global(gp + 8192));
        CP_ASYNC_16(s + 12288, (uint64_t)__cvta_generic_to_global(gp + 12288));
    };

    // prologue: prefetch 3 stages, then convert A while they fly
    load_B(0, 0); CP_COMMIT();
    load_B(1, 1); CP_COMMIT();
    load_B(2, 2); CP_COMMIT();

    // ---- prologue: fp32 x -> e4m3(8x) smem A + exact x_sq (4 thr/row) ----
    {
        const int r  = t >> 2;             // local row 0..63
        const int cb = (t & 3) * 128;      // fp8-col base, 128 cols per thread
        const float* xr = x + (size_t)(rowbase + r) * DDIM + cb;
        float s = 0.f;
        #pragma unroll
        for (int i = 0; i < 8; ++i) {
            const int col = cb + i * 16;
            float4 f0 = reinterpret_cast<const float4*>(xr + i * 16)[0];
            float4 f1 = reinterpret_cast<const float4*>(xr + i * 16)[1];
            float4 f2 = reinterpret_cast<const float4*>(xr + i * 16)[2];
            float4 f3 = reinterpret_cast<const float4*>(xr + i * 16)[3];
            s += f0.x * f0.x + f0.y * f0.y + f0.z * f0.z + f0.w * f0.w
               + f1.x * f1.x + f1.y * f1.y + f1.z * f1.z + f1.w * f1.w
               + f2.x * f2.x + f2.y * f2.y + f2.z * f2.z + f2.w * f2.w
               + f3.x * f3.x + f3.y * f3.y + f3.z * f3.z + f3.w * f3.w;
            uint32_t p0 = pack_f8x4(f0.x * 8.f, f0.y * 8.f, f0.z * 8.f, f0.w * 8.f);
            uint32_t p1 = pack_f8x4(f1.x * 8.f, f1.y * 8.f, f1.z * 8.f, f1.w * 8.f);
            uint32_t p2 = pack_f8x4(f2.x * 8.f, f2.y * 8.f, f2.z * 8.f, f2.w * 8.f);
            uint32_t p3 = pack_f8x4(f3.x * 8.f, f3.y * 8.f, f3.z * 8.f, f3.w * 8.f);
            const int kc = col >> 6, j = (col & 63) >> 4;
            uint32_t dst = sb + kc * 4096 + swz((uint32_t)r, (uint32_t)j);
            asm volatile("st.shared.v4.b32 [%0], {%1, %2, %3, %4};"
                         :: "r"(dst), "r"(p0), "r"(p1), "r"(p2), "r"(p3));
        }
        s += __shfl_xor_sync(0xFFFFFFFFu, s, 1);
        s += __shfl_xor_sync(0xFFFFFFFFu, s, 2);
        if (tid4 == 0) xsq_s[r] = s;
    }
    __syncthreads();

    // this thread's row squared-norms, in registers for all epilogues
    const int er0 = wm * 32 + group;
    float xs[2][2];
    #pragma unroll
    for (int mi = 0; mi < 2; ++mi) {
        xs[mi][0] = xsq_s[er0 + mi * 16];
        xs[mi][1] = xsq_s[er0 + mi * 16 + 8];
    }

    // ---- ldmatrix lane offsets ----
    uint32_t aAddr[2][2];
    {
        int r8   = (l & 7) + (((l >> 3) & 1) << 3);
        int cbit = l >> 4;
        #pragma unroll
        for (int mi = 0; mi < 2; ++mi) {
            int row = wm * 32 + mi * 16 + r8;
            aAddr[mi][0] = swz(row, cbit);
            aAddr[mi][1] = swz(row, 2 + cbit);
        }
    }
    uint32_t bAddr[2][2];
    {
        int m = l >> 3;
        #pragma unroll
        for (int p = 0; p < 2; ++p) {
            int row = wn * 32 + (p * 2 + (m >> 1)) * 8 + (l & 7);
            #pragma unroll
            for (int ks = 0; ks < 2; ++ks)
                bAddr[p][ks] = swz(row, 2 * ks + (m & 1));
        }
    }

    // fp16 accumulators: 2 regs per (mi,nj) fragment
    uint32_t acc[2][4][2];
    #pragma unroll
    for (int mi = 0; mi < 2; ++mi)
        #pragma unroll
        for (int nj = 0; nj < 4; ++nj) { acc[mi][nj][0] = 0u; acc[mi][nj][1] = 0u; }

    float rs[2][2] = {{0.f, 0.f}, {0.f, 0.f}};   // running row sums

    // precomputed output row pointers
    float* outp[2][2];
    #pragma unroll
    for (int mi = 0; mi < 2; ++mi) {
        const int r0 = wm * 32 + mi * 16 + group;
        outp[mi][0] = out + (size_t)(rowbase + r0) * KCL;
        outp[mi][1] = out + (size_t)(rowbase + r0 + 8) * KCL;
    }

    // ---- 8 N-tiles x 4 K-windows; slot == kcp (compile-time) ----
    #pragma unroll 1
    for (int nt = 0; nt < 8; ++nt) {
        #pragma unroll
        for (int kcp = 0; kcp < 4; ++kcp) {
            const int idx = nt * 4 + kcp;
            CP_WAIT_2();
            __syncthreads();
            if (idx + 3 < 32) load_B(idx + 3, (kcp + 3) & 3);
            CP_COMMIT();

            const uint32_t stg = sb + B_OFF + kcp * B_STAGE;
            #pragma unroll
            for (int half = 0; half < 2; ++half) {
                const uint32_t sA = sb + (kcp * 2 + half) * 4096;
                const uint32_t sB = stg + half * 8192;
                #pragma unroll
                for (int ks = 0; ks < 2; ++ks) {
                    uint32_t a[2][4], b[4][2];
                    #pragma unroll
                    for (int mi = 0; mi < 2; ++mi)
                        LDSM_X4(a[mi][0], a[mi][1], a[mi][2], a[mi][3], sA + aAddr[mi][ks]);
                    #pragma unroll
                    for (int p = 0; p < 2; ++p)
                        LDSM_X4(b[2*p][0], b[2*p][1], b[2*p+1][0], b[2*p+1][1],
                                sB + bAddr[p][ks]);
                    #pragma unroll
                    for (int mi = 0; mi < 2; ++mi)
                        #pragma unroll
                        for (int nj = 0; nj < 4; ++nj)
                            MMA_FP8H(acc[mi][nj][0], acc[mi][nj][1],
                                     a[mi][0], a[mi][1], a[mi][2], a[mi][3],
                                     b[nj][0], b[nj][1]);
                }
            }
        }

        // ---- N-tile epilogue (unpack f16 acc; csq via __ldg) ----
        {
            const int ntbase = nt * 128;
            const float kk = 1.f / 256.f;   // 2*cross = acc/256
            #pragma unroll
            for (int mi = 0; mi < 2; ++mi) {
                #pragma unroll
                for (int nj = 0; nj < 4; ++nj) {
                    const int colg = ntbase + wn * 32 + nj * 8 + tid4 * 2;
                    const float cs0 = __ldg(g_csq + colg);
                    const float cs1 = __ldg(g_csq + colg + 1);
                    float2 f0 = __half22float2(*reinterpret_cast<__half2*>(&acc[mi][nj][0]));
                    float2 f1 = __half22float2(*reinterpret_cast<__half2*>(&acc[mi][nj][1]));
                    acc[mi][nj][0] = 0u; acc[mi][nj][1] = 0u;
                    float q00 = __fdividef(1.f, 1.f + fmaxf(xs[mi][0] + cs0 - kk * f0.x, 0.f));
                    float q01 = __fdividef(1.f, 1.f + fmaxf(xs[mi][0] + cs1 - kk * f0.y, 0.f));
                    float q10 = __fdividef(1.f, 1.f + fmaxf(xs[mi][1] + cs0 - kk * f1.x, 0.f));
                    float q11 = __fdividef(1.f, 1.f + fmaxf(xs[mi][1] + cs1 - kk * f1.y, 0.f));
                    rs[mi][0] += q00 + q01;
                    rs[mi][1] += q10 + q11;
                    *reinterpret_cast<float2*>(outp[mi][0] + colg) = make_float2(q00, q01);
                    *reinterpret_cast<float2*>(outp[mi][1] + colg) = make_float2(q10, q11);
                }
            }
        }
    }

    // ---- final row-sum reduction (ps/rsum alias the dead B ring) ----
    CP_WAIT_0();
    __syncthreads();
    float* ps     = reinterpret_cast<float*>(smem + PS_OFF);   // [64][4]
    float* rsum_s = reinterpret_cast<float*>(smem + RSUM_OFF); // [64]
    #pragma unroll
    for (int mi = 0; mi < 2; ++mi) {
        float s0 = rs[mi][0], s1 = rs[mi][1];
        s0 += __shfl_xor_sync(0xFFFFFFFFu, s0, 1);
        s0 += __shfl_xor_sync(0xFFFFFFFFu, s0, 2);
        s1 += __shfl_xor_sync(0xFFFFFFFFu, s1, 1);
        s1 += __shfl_xor_sync(0xFFFFFFFFu, s1, 2);
        if (tid4 == 0) {
            const int r0 = wm * 32 + mi * 16 + group;
            ps[r0 * 4 + wn] = s0;
            ps[(r0 + 8) * 4 + wn] = s1;
        }
    }
    __syncthreads();
    if (t < 64)
        rsum_s[t] = __fdividef(1.f, ps[t * 4 + 0] + ps[t * 4 + 1] +
                                    ps[t * 4 + 2] + ps[t * 4 + 3]);
    __syncthreads();

    // ---- fused renormalization (256KB output slab, L2-resident) ----
    float4* op = reinterpret_cast<float4*>(out + (size_t)rowbase * KCL);
    #pragma unroll 4
    for (int r = 0; r < 64; ++r) {
        float iv = rsum_s[r];
        float4 v = op[(size_t)r * 256 + t];
        v.x *= iv; v.y *= iv; v.z *= iv; v.w *= iv;
        op[(size_t)r * 256 + t] = v;
    }
}

// ============================ launch =======================================
extern "C" void kernel_launch(void* const* d_in, const int* in_sizes, int n_in,
                              void* d_out, int out_size) {
    const float* x  = (const float*)d_in[0];   // (65536, 512)
    const float* cl = (const float*)d_in[1];   // (1024, 512)
    float* out = (float*)d_out;                // (65536, 1024)
    (void)in_sizes; (void)n_in; (void)out_size;

    cudaFuncSetAttribute(cluster_main_kernel,
                         cudaFuncAttributeMaxDynamicSharedMemorySize, SMEM_TOTAL);

    prep_clusters<<<KCL, 128>>>(cl);
    prep_breord<<<KCL, 128>>>();
    cluster_main_kernel<<<NROWS / 64, 256, SMEM_TOTAL>>>(x, out);
}